// round 11
// baseline (speedup 1.0000x reference)
#include <cuda_runtime.h>
#include <cuda_bf16.h>

// EdgeAtt: B=64, L=512, D=512. Two kernels, PDL + per-batch release/acquire
// flags: k_soft CTAs for batch b proceed as soon as k_proj's 64 CTAs of
// batch b have signaled — pipelined overlap of read and write streams.

#define L_DIM 512
#define D_DIM 512
#define SLOPE 0.2f
#define MASKV -1e9f

__device__ float g_ei[64 * L_DIM];
__device__ float g_ej[64 * L_DIM];
__device__ int   g_done[64];

__global__ void k_reset() { g_done[threadIdx.x] = 0; }

// ---------------- kernel 1: dual projection, warp per row ----------------
// 4096 CTAs x 8 warps; CTA covers 8 consecutive rows (single batch).
__global__ void __launch_bounds__(256) k_proj(const float* __restrict__ nf,
                                              const float* __restrict__ wa,
                                              const int* __restrict__ tlen) {
    cudaTriggerProgrammaticLaunchCompletion();   // let k_soft start dispatching

    const int tid  = threadIdx.x;
    const int warp = tid >> 5;
    const int lane = tid & 31;
    const int r    = blockIdx.x * 8 + warp;      // global row
    const int b    = r >> 9;
    const int l    = r & (L_DIM - 1);
    const int len  = __ldg(&tlen[b]);

    if (l < len) {                               // unused projections skipped
        const float4* row = reinterpret_cast<const float4*>(nf + (size_t)r * D_DIM);
        const float4* w1  = reinterpret_cast<const float4*>(wa);
        const float4* w2  = reinterpret_cast<const float4*>(wa + D_DIM);

        float s1 = 0.f, s2 = 0.f;
#pragma unroll
        for (int t = 0; t < 4; t++) {
            int idx = lane + t * 32;
            float4 v = row[idx];
            float4 a = __ldg(&w1[idx]);
            float4 w = __ldg(&w2[idx]);
            s1 += v.x * a.x + v.y * a.y + v.z * a.z + v.w * a.w;
            s2 += v.x * w.x + v.y * w.y + v.z * w.z + v.w * w.w;
        }
#pragma unroll
        for (int o = 16; o; o >>= 1) {
            s1 += __shfl_xor_sync(0xffffffffu, s1, o);
            s2 += __shfl_xor_sync(0xffffffffu, s2, o);
        }
        if (lane == 0) { g_ei[r] = s1; g_ej[r] = s2; }
    }

    // release: cta-sync chains all warps' writes into tid0's gpu-scope release
    __syncthreads();
    if (tid == 0) {
        __threadfence();
        atomicAdd(&g_done[b], 1);
    }
}

// ---------------- kernel 2: masked softmax, warp per output row ----------------
__global__ void __launch_bounds__(256) k_soft(const float* __restrict__ ba,
                                              const int* __restrict__ tlen,
                                              float* __restrict__ out) {
    __shared__ float sej[L_DIM];
    __shared__ float smax[8];

    const int b    = blockIdx.y;
    const int tid  = threadIdx.x;
    const int warp = tid >> 5;
    const int lane = tid & 31;
    const int len  = __ldg(&tlen[b]);            // input only: no dependency
    const int i    = blockIdx.x * 8 + warp;

    float4* orow4 = reinterpret_cast<float4*>(out + ((size_t)b * L_DIM + i) * L_DIM);

    // ---- independent prologue: zero rows (overlaps k_proj) ----
    if (i >= len) {
        float4 z = make_float4(0.f, 0.f, 0.f, 0.f);
#pragma unroll
        for (int t = 0; t < 4; t++) orow4[t * 32 + lane] = z;
        if (blockIdx.x * 8 >= len) return;       // whole CTA invalid: done
    }

    // ---- per-batch acquire: wait only for this batch's projections ----
    if (tid == 0) {
        int v;
        do {
            asm volatile("ld.global.acquire.gpu.b32 %0, [%1];"
                         : "=r"(v) : "l"(&g_done[b]) : "memory");
        } while (v < 64);
    }
    __syncthreads();

    // premasked e_j: j>=len -> -1e9 (exp underflows to exact 0)
    const float v0 = (tid       < len) ? g_ej[b * L_DIM + tid]       : MASKV;
    const float v1 = (tid + 256 < len) ? g_ej[b * L_DIM + tid + 256] : MASKV;
    sej[tid]       = v0;
    sej[tid + 256] = v1;

    // block max of premasked e_j (len >= 1)
    float mv = fmaxf(v0, v1);
#pragma unroll
    for (int o = 16; o; o >>= 1) mv = fmaxf(mv, __shfl_xor_sync(0xffffffffu, mv, o));
    if (lane == 0) smax[warp] = mv;
    __syncthreads();
    float mxej = smax[0];
#pragma unroll
    for (int k = 1; k < 8; k++) mxej = fmaxf(mxej, smax[k]);

    if (i >= len) return;                        // zero row already written

    const float ei   = g_ei[b * L_DIM + i] + __ldg(ba);
    const float mraw = ei + mxej;
    const float m    = fmaxf(mraw, SLOPE * mraw);   // exact row max (monotonic lrelu)

    float4 p[4];
    float s = 0.f;
#pragma unroll
    for (int t = 0; t < 4; t++) {
        const int j0 = t * 128 + lane * 4;
        float4 e4 = *reinterpret_cast<const float4*>(&sej[j0]);

        float v, lr, pe;
        v = ei + e4.x; lr = fmaxf(v, SLOPE * v);
        pe = __expf(lr - m); p[t].x = pe; s += pe;
        v = ei + e4.y; lr = fmaxf(v, SLOPE * v);
        pe = __expf(lr - m); p[t].y = pe; s += pe;
        v = ei + e4.z; lr = fmaxf(v, SLOPE * v);
        pe = __expf(lr - m); p[t].z = pe; s += pe;
        v = ei + e4.w; lr = fmaxf(v, SLOPE * v);
        pe = __expf(lr - m); p[t].w = pe; s += pe;
    }
#pragma unroll
    for (int o = 16; o; o >>= 1) s += __shfl_xor_sync(0xffffffffu, s, o);

    const float inv = 1.f / s;
#pragma unroll
    for (int t = 0; t < 4; t++) {
        float4 r;
        r.x = p[t].x * inv; r.y = p[t].y * inv;
        r.z = p[t].z * inv; r.w = p[t].w * inv;
        orow4[t * 32 + lane] = r;
    }
}

extern "C" void kernel_launch(void* const* d_in, const int* in_sizes, int n_in,
                              void* d_out, int out_size) {
    const float* nf   = (const float*)d_in[0];   // [B, L, D]
    const float* wa   = (const float*)d_in[1];   // [2D]
    const float* ba   = (const float*)d_in[2];   // [1]
    const int*   tlen = (const int*)d_in[3];     // [B]
    float* out = (float*)d_out;                  // [B, L, L]

    const int B = in_sizes[3];

    k_reset<<<1, B>>>();
    k_proj<<<B * L_DIM / 8, 256>>>(nf, wa, tlen);

    // PDL so k_soft dispatches while k_proj runs; per-batch flags gate the
    // actual data dependency.
    cudaLaunchConfig_t cfg = {};
    cfg.gridDim  = dim3(L_DIM / 8, (unsigned)B, 1);
    cfg.blockDim = dim3(256, 1, 1);
    cfg.dynamicSmemBytes = 0;
    cfg.stream = 0;
    cudaLaunchAttribute attr[1];
    attr[0].id = cudaLaunchAttributeProgrammaticStreamSerialization;
    attr[0].val.programmaticStreamSerializationAllowed = 1;
    cfg.attrs = attr;
    cfg.numAttrs = 1;
    cudaLaunchKernelEx(&cfg, k_soft, ba, tlen, out);
}